// round 1
// baseline (speedup 1.0000x reference)
#include <cuda_runtime.h>

// FeatNeighbourCorr: out[b,k,h,w] = <n(p), n(q_k)>, n = feats / ||feats||_C,
// q_k = reflect(h - ox_k, w - oy_k), offsets (1,0)(1,1)(0,1)(-1,1)(-1,0)(-1,-1)(0,-1)(1,-1)

#define HH 256
#define WW 256
#define CC 128
#define TH 32
#define TW 32
#define KC 8
#define NCHUNK (CC / KC)
#define TILE 34          // TH + 2 halo
#define TSTR 35          // padded row stride (conflict-free)
#define NTHREADS 256
#define NPIX (TILE * TILE)   // 1156

__global__ __launch_bounds__(NTHREADS)
void featcorr_fused_kernel(const float* __restrict__ feats,
                           float* __restrict__ out) {
    __shared__ float s[KC][TILE * TSTR];
    __shared__ float rn[NPIX];

    const int t  = threadIdx.x;
    const int b  = blockIdx.z;
    const int h0 = blockIdx.y * TH;
    const int w0 = blockIdx.x * TW;

    // ---- precompute this thread's load slots (chunk/channel invariant) ----
    int  goff[5], soff[5];
    bool valid[5];
    float ss[5];
#pragma unroll
    for (int u = 0; u < 5; ++u) {
        int i = t + u * NTHREADS;
        valid[u] = (i < NPIX);
        int ii = valid[u] ? i : 0;
        int yy = ii / TILE;
        int xx = ii - yy * TILE;
        int gh = h0 + yy - 1;
        gh = (gh < 0) ? -gh : ((gh >= HH) ? 2 * HH - 2 - gh : gh);
        int gw = w0 + xx - 1;
        gw = (gw < 0) ? -gw : ((gw >= WW) ? 2 * WW - 2 - gw : gw);
        goff[u] = gh * WW + gw;
        soff[u] = yy * TSTR + xx;
        ss[u]   = 0.f;
    }

    // thread -> 1x4 output strip: row py, cols px0..px0+3
    const int py  = t >> 3;
    const int px0 = (t & 7) << 2;

    float acc[4][8];
#pragma unroll
    for (int i = 0; i < 4; ++i)
#pragma unroll
        for (int k = 0; k < 8; ++k) acc[i][k] = 0.f;

    const float* fb = feats + (size_t)b * CC * HH * WW;

    for (int ch = 0; ch < NCHUNK; ++ch) {
        const float* fc = fb + (size_t)(ch * KC) * (HH * WW);

        // ---- stage chunk into smem; sum-of-squares for free ----
#pragma unroll
        for (int c = 0; c < KC; ++c) {
            const float* fp = fc + (size_t)c * (HH * WW);
#pragma unroll
            for (int u = 0; u < 5; ++u) {
                if (valid[u]) {
                    float v = __ldg(fp + goff[u]);
                    s[c][soff[u]] = v;
                    ss[u] += v * v;
                }
            }
        }
        __syncthreads();

        // ---- 8-neighbor dot accumulation, register sliding window ----
#pragma unroll
        for (int c = 0; c < KC; ++c) {
            const float* r0 = &s[c][py * TSTR + px0];
            float tr[6], mr[6], br[6];
#pragma unroll
            for (int j = 0; j < 6; ++j) {
                tr[j] = r0[j];
                mr[j] = r0[TSTR + j];
                br[j] = r0[2 * TSTR + j];
            }
#pragma unroll
            for (int i = 0; i < 4; ++i) {
                float cv = mr[i + 1];
                acc[i][0] += cv * tr[i + 1];  // ( 1, 0) -> (y-1, x  )
                acc[i][1] += cv * tr[i];      // ( 1, 1) -> (y-1, x-1)
                acc[i][2] += cv * mr[i];      // ( 0, 1) -> (y  , x-1)
                acc[i][3] += cv * br[i];      // (-1, 1) -> (y+1, x-1)
                acc[i][4] += cv * br[i + 1];  // (-1, 0) -> (y+1, x  )
                acc[i][5] += cv * br[i + 2];  // (-1,-1) -> (y+1, x+1)
                acc[i][6] += cv * mr[i + 2];  // ( 0,-1) -> (y  , x+1)
                acc[i][7] += cv * tr[i + 2];  // ( 1,-1) -> (y-1, x+1)
            }
        }
        __syncthreads();
    }

    // ---- ssq -> rsqrt in smem ----
#pragma unroll
    for (int u = 0; u < 5; ++u)
        if (valid[u]) rn[t + u * NTHREADS] = rsqrtf(ss[u]);
    __syncthreads();

    // ---- apply norms, write float4 per output channel ----
    const int roff[8] = {-TILE, -TILE - 1, -1, TILE - 1, TILE, TILE + 1, 1, -TILE + 1};
    float* ob = out + ((size_t)b * 8) * (HH * WW) + (size_t)(h0 + py) * WW + (w0 + px0);

    float rc[4];
    int   ci[4];
#pragma unroll
    for (int i = 0; i < 4; ++i) {
        ci[i] = (py + 1) * TILE + (px0 + 1 + i);
        rc[i] = rn[ci[i]];
    }
#pragma unroll
    for (int k = 0; k < 8; ++k) {
        float4 v;
        v.x = acc[0][k] * rc[0] * rn[ci[0] + roff[k]];
        v.y = acc[1][k] * rc[1] * rn[ci[1] + roff[k]];
        v.z = acc[2][k] * rc[2] * rn[ci[2] + roff[k]];
        v.w = acc[3][k] * rc[3] * rn[ci[3] + roff[k]];
        *reinterpret_cast<float4*>(ob + (size_t)k * (HH * WW)) = v;
    }
}

extern "C" void kernel_launch(void* const* d_in, const int* in_sizes, int n_in,
                              void* d_out, int out_size) {
    const float* feats = (const float*)d_in[0];
    float* out = (float*)d_out;
    dim3 grid(WW / TW, HH / TH, 8);
    featcorr_fused_kernel<<<grid, NTHREADS>>>(feats, out);
}